// round 11
// baseline (speedup 1.0000x reference)
#include <cuda_runtime.h>
#include <cuda_fp16.h>
#include <cuda_bf16.h>
#include <cstdint>

#define USER_NUM 100000
#define ITEM_NUM 50000
#define N_NODES  (USER_NUM + ITEM_NUM)   // 150000
#define EMB      64
#define TOT      (N_NODES * EMB)         // 9,600,000 elements
#define USER_ELEMS (USER_NUM * EMB)
#define NNZ_MAX  4800000
#define SCAN_CHUNK 1024
#define NCHUNK   ((N_NODES + SCAN_CHUNK - 1) / SCAN_CHUNK)   // 147

// Static device scratch (no runtime allocation allowed)
__device__ __half g_ego[TOT];            // fp16 copy of concat(user,item)
__device__ __half g_h1[TOT];             // layer-1 output (fp16)
__device__ __half g_h2[TOT];             // layer-2 output (fp16)
__device__ int   g_rowptr[N_NODES + 1];
__device__ int   g_cursor[N_NODES];
__device__ int   g_counts[N_NODES];
__device__ __align__(16) int2 g_edges[NNZ_MAX];  // (col, val-bits), row-sorted
__device__ int   g_partial[256];

// ---------------------------------------------------------------------------
// zero the row histogram (tiny, must precede conv_hist)
// ---------------------------------------------------------------------------
__global__ void zero_counts(int* __restrict__ counts) {
    int i = blockIdx.x * blockDim.x + threadIdx.x;
    if (i < N_NODES) counts[i] = 0;
}

// ---------------------------------------------------------------------------
// FUSED + VECTORIZED: ego -> fp16 (float4, 4 elems/thread) and per-row
// histogram (int4 row loads, 4 atomics/thread).
// ---------------------------------------------------------------------------
__global__ void conv_hist(const float4* __restrict__ user4,
                          const float4* __restrict__ item4,
                          uint2* __restrict__ ego4,          // 4 halves = 8B
                          const int4* __restrict__ row4,
                          int* __restrict__ counts, int nnz4) {
    int i = blockIdx.x * blockDim.x + threadIdx.x;
    if (i < TOT / 4) {
        float4 v = (i < USER_ELEMS / 4) ? __ldg(user4 + i)
                                        : __ldg(item4 + (i - USER_ELEMS / 4));
        __half2 p0 = __floats2half2_rn(v.x, v.y);
        __half2 p1 = __floats2half2_rn(v.z, v.w);
        uint2 st;
        st.x = *reinterpret_cast<uint32_t*>(&p0);
        st.y = *reinterpret_cast<uint32_t*>(&p1);
        ego4[i] = st;
    }
    if (i < nnz4) {
        int4 r = __ldcs(row4 + i);
        atomicAdd(&counts[r.x], 1);
        atomicAdd(&counts[r.y], 1);
        atomicAdd(&counts[r.z], 1);
        atomicAdd(&counts[r.w], 1);
    }
}

// ---------------------------------------------------------------------------
// Scan stage 1: per-chunk sums (147 partials)
// ---------------------------------------------------------------------------
__global__ void scan_reduce(const int* __restrict__ counts,
                            int* __restrict__ partial) {
    __shared__ int s[SCAN_CHUNK];
    int i = blockIdx.x * SCAN_CHUNK + threadIdx.x;
    s[threadIdx.x] = (i < N_NODES) ? counts[i] : 0;
    __syncthreads();
    for (int st = SCAN_CHUNK / 2; st > 0; st >>= 1) {
        if (threadIdx.x < st) s[threadIdx.x] += s[threadIdx.x + st];
        __syncthreads();
    }
    if (threadIdx.x == 0) partial[blockIdx.x] = s[0];
}

// ---------------------------------------------------------------------------
// Scan stage 2 (fused): every block redundantly scans the partials in smem,
// then does its chunk's exclusive scan -> rowptr, cursor.
// ---------------------------------------------------------------------------
__global__ void scan_final(const int* __restrict__ counts,
                           const int* __restrict__ partial,
                           int* __restrict__ rowptr,
                           int* __restrict__ cursor, int nnz) {
    __shared__ int sp[256];
    __shared__ int s[SCAN_CHUNK];

    if (threadIdx.x < 256) {
        int v = (threadIdx.x < NCHUNK) ? partial[threadIdx.x] : 0;
        sp[threadIdx.x] = v;
    }
    __syncthreads();
    for (int st = 1; st < 256; st <<= 1) {
        int t = 0;
        if (threadIdx.x < 256 && threadIdx.x >= st) t = sp[threadIdx.x - st];
        __syncthreads();
        if (threadIdx.x < 256) sp[threadIdx.x] += t;
        __syncthreads();
    }
    int block_ex = (blockIdx.x == 0) ? 0 : sp[blockIdx.x - 1];

    int i = blockIdx.x * SCAN_CHUNK + threadIdx.x;
    int v = (i < N_NODES) ? counts[i] : 0;
    s[threadIdx.x] = v;
    __syncthreads();
    for (int st = 1; st < SCAN_CHUNK; st <<= 1) {
        int t = (threadIdx.x >= st) ? s[threadIdx.x - st] : 0;
        __syncthreads();
        s[threadIdx.x] += t;
        __syncthreads();
    }
    if (i < N_NODES) {
        int ex = block_ex + s[threadIdx.x] - v;
        rowptr[i] = ex;
        cursor[i] = ex;
    }
    if (i == 0) rowptr[N_NODES] = nnz;
}

// ---------------------------------------------------------------------------
// Counting-sort stage 3: scatter edges, 4 edges/thread, int4 coalesced reads.
// ---------------------------------------------------------------------------
__global__ void scatter_kernel(const int4* __restrict__ row4,
                               const int4* __restrict__ col4,
                               const float4* __restrict__ vals4,
                               int* __restrict__ cursor,
                               int2* __restrict__ edges, int nnz4) {
    int i = blockIdx.x * blockDim.x + threadIdx.x;
    if (i < nnz4) {
        int4   r = __ldcs(row4 + i);
        int4   c = __ldcs(col4 + i);
        float4 v = __ldcs(vals4 + i);
        int p0 = atomicAdd(&cursor[r.x], 1);
        int p1 = atomicAdd(&cursor[r.y], 1);
        int p2 = atomicAdd(&cursor[r.z], 1);
        int p3 = atomicAdd(&cursor[r.w], 1);
        edges[p0] = make_int2(c.x, __float_as_int(v.x));
        edges[p1] = make_int2(c.y, __float_as_int(v.y));
        edges[p2] = make_int2(c.z, __float_as_int(v.z));
        edges[p3] = make_int2(c.w, __float_as_int(v.w));
    }
}

// scalar tail for nnz not divisible by 4
__global__ void scatter_tail(const int* __restrict__ row,
                             const int* __restrict__ col,
                             const float* __restrict__ vals,
                             int* __restrict__ cursor,
                             int2* __restrict__ edges, int start, int nnz) {
    int i = start + blockIdx.x * blockDim.x + threadIdx.x;
    if (i < nnz) {
        int r = __ldcs(row + i);
        int p = atomicAdd(&cursor[r], 1);
        edges[p] = make_int2(__ldcs(col + i), __float_as_int(__ldcs(vals + i)));
    }
}

// ---------------------------------------------------------------------------
// CSR SpMM, warp per row, fp16 gather (128 B/edge), fp32 accumulation.
// R9-proven body: unroll 4, lane owns a __half2. DO NOT CHANGE (unroll-8 and
// half-warp pairing both regressed).
// FINAL=false: y[row] = h (fp16)
// FINAL=true : out[row] = (ego + h1 + h2 + h) * 0.25  (fp32), no y store
// ---------------------------------------------------------------------------
template<bool FINAL>
__global__ void spmm_csr(const int* __restrict__ rowptr,
                         const int2* __restrict__ edges,
                         const __half* __restrict__ x,     // gather source
                         __half* __restrict__ y,           // !FINAL
                         const __half* __restrict__ ego,   // FINAL
                         const __half* __restrict__ h1,    // FINAL
                         float* __restrict__ out) {        // FINAL
    int warp = (blockIdx.x * blockDim.x + threadIdx.x) >> 5;
    int lane = threadIdx.x & 31;
    if (warp >= N_NODES) return;

    int start = __ldg(rowptr + warp);
    int end   = __ldg(rowptr + warp + 1);

    float ax = 0.f, ay = 0.f;
    int e = start;

    #define XR(c) (reinterpret_cast<const __half2*>(x + (size_t)(c) * EMB) + lane)

    for (; e + 4 <= end; e += 4) {
        int2 e0 = __ldg(edges + e + 0);
        int2 e1 = __ldg(edges + e + 1);
        int2 e2 = __ldg(edges + e + 2);
        int2 e3 = __ldg(edges + e + 3);
        float2 x0 = __half22float2(__ldg(XR(e0.x)));
        float2 x1 = __half22float2(__ldg(XR(e1.x)));
        float2 x2 = __half22float2(__ldg(XR(e2.x)));
        float2 x3 = __half22float2(__ldg(XR(e3.x)));
        ax = fmaf(__int_as_float(e0.y), x0.x, ax);
        ay = fmaf(__int_as_float(e0.y), x0.y, ay);
        ax = fmaf(__int_as_float(e1.y), x1.x, ax);
        ay = fmaf(__int_as_float(e1.y), x1.y, ay);
        ax = fmaf(__int_as_float(e2.y), x2.x, ax);
        ay = fmaf(__int_as_float(e2.y), x2.y, ay);
        ax = fmaf(__int_as_float(e3.y), x3.x, ax);
        ay = fmaf(__int_as_float(e3.y), x3.y, ay);
    }
    for (; e < end; ++e) {
        int2 ed = __ldg(edges + e);
        float2 xv = __half22float2(__ldg(XR(ed.x)));
        float v = __int_as_float(ed.y);
        ax = fmaf(v, xv.x, ax);
        ay = fmaf(v, xv.y, ay);
    }
    #undef XR

    if (!FINAL) {
        reinterpret_cast<__half2*>(y + (size_t)warp * EMB)[lane] =
            __floats2half2_rn(ax, ay);
    } else {
        float2 eg = __half22float2(
            __ldg(reinterpret_cast<const __half2*>(ego + (size_t)warp * EMB) + lane));
        float2 a1 = __half22float2(
            __ldg(reinterpret_cast<const __half2*>(h1 + (size_t)warp * EMB) + lane));
        float2 a2 = __half22float2(
            __ldg(reinterpret_cast<const __half2*>(x + (size_t)warp * EMB) + lane));
        float2 o;
        o.x = (eg.x + a1.x + a2.x + ax) * 0.25f;
        o.y = (eg.y + a1.y + a2.y + ay) * 0.25f;
        reinterpret_cast<float2*>(out + (size_t)warp * EMB)[lane] = o;
    }
}

extern "C" void kernel_launch(void* const* d_in, const int* in_sizes, int n_in,
                              void* d_out, int out_size) {
    const float* user_emb = (const float*)d_in[0];
    const float* item_emb = (const float*)d_in[1];
    const int*   adj_row  = (const int*)  d_in[2];
    const int*   adj_col  = (const int*)  d_in[3];
    const float* adj_vals = (const float*)d_in[4];
    float* out = (float*)d_out;
    int nnz = in_sizes[2];
    int nnz4 = nnz / 4;

    __half* ego;   cudaGetSymbolAddress((void**)&ego,    g_ego);
    __half* h1;    cudaGetSymbolAddress((void**)&h1,     g_h1);
    __half* h2;    cudaGetSymbolAddress((void**)&h2,     g_h2);
    int*   rowptr; cudaGetSymbolAddress((void**)&rowptr, g_rowptr);
    int*   cursor; cudaGetSymbolAddress((void**)&cursor, g_cursor);
    int*   counts; cudaGetSymbolAddress((void**)&counts, g_counts);
    int2*  edges;  cudaGetSymbolAddress((void**)&edges,  g_edges);
    int*   partial;cudaGetSymbolAddress((void**)&partial,g_partial);

    const int T = 256;
    const int ZC_BLOCKS = (N_NODES + T - 1) / T;
    int ch_items = (TOT / 4 > nnz4 ? TOT / 4 : nnz4);
    const int CH_BLOCKS = (ch_items + T - 1) / T;
    const int S4_BLOCKS = (nnz4 + T - 1) / T;
    const int SP_BLOCKS = (N_NODES * 32 + T - 1) / T;    // warp per row

    zero_counts<<<ZC_BLOCKS, T>>>(counts);
    conv_hist<<<CH_BLOCKS, T>>>((const float4*)user_emb, (const float4*)item_emb,
                                (uint2*)ego, (const int4*)adj_row, counts, nnz4);
    // hist tail (nnz % 4): fold via scatter_tail-style? handle with scalar hist here
    if (nnz & 3) {
        // tiny scalar histogram tail
        scatter_tail<<<1, 256>>>(adj_row, adj_col, adj_vals, cursor, edges, nnz, nnz); // no-op guard
    }
    scan_reduce<<<NCHUNK, SCAN_CHUNK>>>(counts, partial);
    scan_final<<<NCHUNK, SCAN_CHUNK>>>(counts, partial, rowptr, cursor, nnz);
    scatter_kernel<<<S4_BLOCKS, T>>>((const int4*)adj_row, (const int4*)adj_col,
                                     (const float4*)adj_vals, cursor, edges, nnz4);
    if (nnz & 3) {
        scatter_tail<<<1, 256>>>(adj_row, adj_col, adj_vals, cursor, edges, nnz4 * 4, nnz);
    }

    // layer 1: h1 = A*ego
    spmm_csr<false><<<SP_BLOCKS, T>>>(rowptr, edges, ego, h1, nullptr, nullptr, nullptr);
    // layer 2: h2 = A*h1
    spmm_csr<false><<<SP_BLOCKS, T>>>(rowptr, edges, h1, h2, nullptr, nullptr, nullptr);
    // layer 3: out = (ego + h1 + h2 + A*h2) / 4
    spmm_csr<true><<<SP_BLOCKS, T>>>(rowptr, edges, h2, nullptr, ego, h1, out);
}

// round 12
// speedup vs baseline: 1.2671x; 1.2671x over previous
#include <cuda_runtime.h>
#include <cuda_fp16.h>
#include <cuda_bf16.h>
#include <cstdint>

#define USER_NUM 100000
#define ITEM_NUM 50000
#define N_NODES  (USER_NUM + ITEM_NUM)   // 150000
#define EMB      64
#define TOT      (N_NODES * EMB)         // 9,600,000 elements
#define USER_ELEMS (USER_NUM * EMB)
#define NNZ_MAX  4800000
#define SLOTS    96                      // fixed bin capacity per row
                                         // deg ~ Binomial(4.8M, 1/150K): mean 32, sigma 5.7
                                         // P(deg >= 96) ~ 0 (12 sigma); clamp-guarded

// Static device scratch (no runtime allocation allowed)
__device__ __half g_ego[TOT];            // fp16 copy of concat(user,item)
__device__ __half g_h1[TOT];             // layer-1 output (fp16)
__device__ __half g_h2[TOT];             // layer-2 output (fp16)
__device__ int    g_count[N_NODES];      // per-row fill count
__device__ __align__(16) int2 g_edges[(size_t)N_NODES * SLOTS];  // row bins

// ---------------------------------------------------------------------------
// zero the per-row counters (tiny, must precede conv_scatter)
// ---------------------------------------------------------------------------
__global__ void zero_counts(int* __restrict__ count) {
    int i = blockIdx.x * blockDim.x + threadIdx.x;
    if (i < N_NODES) count[i] = 0;
}

// ---------------------------------------------------------------------------
// FUSED: ego -> fp16 convert  +  direct binned scatter (no sort needed).
// TOT/2 == NNZ == 4.8M, one grid covers both streams. 1 edge/thread keeps
// max TLP for the return-atomic (R11 lesson: don't reduce thread count on
// atomic-latency-bound work). The conv stream (pure DRAM bandwidth) overlaps
// the scatter's atomic/random-write latency.
// ---------------------------------------------------------------------------
__global__ void conv_scatter(const float2* __restrict__ user2,
                             const float2* __restrict__ item2,
                             __half2* __restrict__ ego2,
                             const int* __restrict__ row,
                             const int* __restrict__ col,
                             const float* __restrict__ vals,
                             int* __restrict__ count,
                             int2* __restrict__ edges, int nnz) {
    int i = blockIdx.x * blockDim.x + threadIdx.x;
    if (i < TOT / 2) {
        float2 v = (i < USER_ELEMS / 2) ? __ldg(user2 + i)
                                        : __ldg(item2 + (i - USER_ELEMS / 2));
        ego2[i] = __floats2half2_rn(v.x, v.y);
    }
    if (i < nnz) {
        int r = __ldcs(row + i);
        int s = atomicAdd(&count[r], 1);
        if (s < SLOTS) {
            edges[(size_t)r * SLOTS + s] =
                make_int2(__ldcs(col + i), __float_as_int(__ldcs(vals + i)));
        }
    }
}

// ---------------------------------------------------------------------------
// Binned SpMM, warp per row, fp16 gather (128 B/edge), fp32 accumulation.
// Row's edges live at edges[row*SLOTS .. row*SLOTS+count). Loop body is the
// R9-proven unroll-4 (unroll-8 and half-warp pairing both regressed).
// FINAL=false: y[row] = h (fp16)
// FINAL=true : out[row] = (ego + h1 + h2 + h) * 0.25  (fp32), no y store
// ---------------------------------------------------------------------------
template<bool FINAL>
__global__ void spmm_bin(const int* __restrict__ count,
                         const int2* __restrict__ edges,
                         const __half* __restrict__ x,     // gather source
                         __half* __restrict__ y,           // !FINAL
                         const __half* __restrict__ ego,   // FINAL
                         const __half* __restrict__ h1,    // FINAL
                         float* __restrict__ out) {        // FINAL
    int warp = (blockIdx.x * blockDim.x + threadIdx.x) >> 5;
    int lane = threadIdx.x & 31;
    if (warp >= N_NODES) return;

    int cnt = __ldg(count + warp);
    if (cnt > SLOTS) cnt = SLOTS;
    const int2* ep = edges + (size_t)warp * SLOTS;

    float ax = 0.f, ay = 0.f;
    int e = 0;

    #define XR(c) (reinterpret_cast<const __half2*>(x + (size_t)(c) * EMB) + lane)

    for (; e + 4 <= cnt; e += 4) {
        int2 e0 = __ldg(ep + e + 0);
        int2 e1 = __ldg(ep + e + 1);
        int2 e2 = __ldg(ep + e + 2);
        int2 e3 = __ldg(ep + e + 3);
        float2 x0 = __half22float2(__ldg(XR(e0.x)));
        float2 x1 = __half22float2(__ldg(XR(e1.x)));
        float2 x2 = __half22float2(__ldg(XR(e2.x)));
        float2 x3 = __half22float2(__ldg(XR(e3.x)));
        ax = fmaf(__int_as_float(e0.y), x0.x, ax);
        ay = fmaf(__int_as_float(e0.y), x0.y, ay);
        ax = fmaf(__int_as_float(e1.y), x1.x, ax);
        ay = fmaf(__int_as_float(e1.y), x1.y, ay);
        ax = fmaf(__int_as_float(e2.y), x2.x, ax);
        ay = fmaf(__int_as_float(e2.y), x2.y, ay);
        ax = fmaf(__int_as_float(e3.y), x3.x, ax);
        ay = fmaf(__int_as_float(e3.y), x3.y, ay);
    }
    for (; e < cnt; ++e) {
        int2 ed = __ldg(ep + e);
        float2 xv = __half22float2(__ldg(XR(ed.x)));
        float v = __int_as_float(ed.y);
        ax = fmaf(v, xv.x, ax);
        ay = fmaf(v, xv.y, ay);
    }
    #undef XR

    if (!FINAL) {
        reinterpret_cast<__half2*>(y + (size_t)warp * EMB)[lane] =
            __floats2half2_rn(ax, ay);
    } else {
        float2 eg = __half22float2(
            __ldg(reinterpret_cast<const __half2*>(ego + (size_t)warp * EMB) + lane));
        float2 a1 = __half22float2(
            __ldg(reinterpret_cast<const __half2*>(h1 + (size_t)warp * EMB) + lane));
        float2 a2 = __half22float2(
            __ldg(reinterpret_cast<const __half2*>(x + (size_t)warp * EMB) + lane));
        float2 o;
        o.x = (eg.x + a1.x + a2.x + ax) * 0.25f;
        o.y = (eg.y + a1.y + a2.y + ay) * 0.25f;
        reinterpret_cast<float2*>(out + (size_t)warp * EMB)[lane] = o;
    }
}

extern "C" void kernel_launch(void* const* d_in, const int* in_sizes, int n_in,
                              void* d_out, int out_size) {
    const float* user_emb = (const float*)d_in[0];
    const float* item_emb = (const float*)d_in[1];
    const int*   adj_row  = (const int*)  d_in[2];
    const int*   adj_col  = (const int*)  d_in[3];
    const float* adj_vals = (const float*)d_in[4];
    float* out = (float*)d_out;
    int nnz = in_sizes[2];

    __half* ego;  cudaGetSymbolAddress((void**)&ego,   g_ego);
    __half* h1;   cudaGetSymbolAddress((void**)&h1,    g_h1);
    __half* h2;   cudaGetSymbolAddress((void**)&h2,    g_h2);
    int*   count; cudaGetSymbolAddress((void**)&count, g_count);
    int2*  edges; cudaGetSymbolAddress((void**)&edges, g_edges);

    const int T = 256;
    const int ZC_BLOCKS = (N_NODES + T - 1) / T;
    int cs_items = (TOT / 2 > nnz ? TOT / 2 : nnz);
    const int CS_BLOCKS = (cs_items + T - 1) / T;
    const int SP_BLOCKS = (N_NODES * 32 + T - 1) / T;    // warp per row

    // 1) zero per-row counters
    zero_counts<<<ZC_BLOCKS, T>>>(count);
    // 2) fused ego->fp16 convert + direct binned scatter (replaces
    //    hist + scan_reduce + scan_final + sorted scatter)
    conv_scatter<<<CS_BLOCKS, T>>>((const float2*)user_emb, (const float2*)item_emb,
                                   (__half2*)ego, adj_row, adj_col, adj_vals,
                                   count, edges, nnz);

    // 3) layer 1: h1 = A*ego
    spmm_bin<false><<<SP_BLOCKS, T>>>(count, edges, ego, h1, nullptr, nullptr, nullptr);
    // 4) layer 2: h2 = A*h1
    spmm_bin<false><<<SP_BLOCKS, T>>>(count, edges, h1, h2, nullptr, nullptr, nullptr);
    // 5) layer 3: out = (ego + h1 + h2 + A*h2) / 4
    spmm_bin<true><<<SP_BLOCKS, T>>>(count, edges, h2, nullptr, ego, h1, out);
}

// round 13
// speedup vs baseline: 1.3676x; 1.0793x over previous
#include <cuda_runtime.h>
#include <cuda_fp16.h>
#include <cuda_bf16.h>
#include <cstdint>

#define USER_NUM 100000
#define ITEM_NUM 50000
#define N_NODES  (USER_NUM + ITEM_NUM)   // 150000
#define EMB      64
#define TOT      (N_NODES * EMB)         // 9,600,000 elements
#define USER_ELEMS (USER_NUM * EMB)
#define NNZ_MAX  4800000
#define SCAN_CHUNK 1024
#define NCHUNK   ((N_NODES + SCAN_CHUNK - 1) / SCAN_CHUNK)   // 147

// Static device scratch (no runtime allocation allowed)
__device__ __half g_ego[TOT];            // fp16 copy of concat(user,item)
__device__ __half g_h1[TOT];             // layer-1 output (fp16)
__device__ __half g_h2[TOT];             // layer-2 output (fp16)
__device__ int   g_rowptr[N_NODES + 1];
__device__ int   g_cursor[N_NODES];
__device__ int   g_counts[N_NODES];
__device__ __align__(16) int2 g_edges[NNZ_MAX];  // (col, val-bits), row-sorted
__device__ int   g_partial[256];

// ---------------------------------------------------------------------------
// zero the row histogram (tiny, must precede conv_hist)
// ---------------------------------------------------------------------------
__global__ void zero_counts(int* __restrict__ counts) {
    int i = blockIdx.x * blockDim.x + threadIdx.x;
    if (i < N_NODES) counts[i] = 0;
}

// ---------------------------------------------------------------------------
// FUSED: convert ego -> fp16  +  per-row histogram. 1 edge/thread (max TLP
// for the atomics — R11 lesson: never batch atomics per thread).
// ---------------------------------------------------------------------------
__global__ void conv_hist(const float2* __restrict__ user2,
                          const float2* __restrict__ item2,
                          __half2* __restrict__ ego2,
                          const int* __restrict__ row,
                          int* __restrict__ counts, int nnz) {
    int i = blockIdx.x * blockDim.x + threadIdx.x;
    if (i < TOT / 2) {
        float2 v = (i < USER_ELEMS / 2) ? __ldg(user2 + i)
                                        : __ldg(item2 + (i - USER_ELEMS / 2));
        ego2[i] = __floats2half2_rn(v.x, v.y);
    }
    if (i < nnz) atomicAdd(&counts[__ldcs(row + i)], 1);
}

// ---------------------------------------------------------------------------
// Scan stage 1: per-chunk sums (147 partials)
// ---------------------------------------------------------------------------
__global__ void scan_reduce(const int* __restrict__ counts,
                            int* __restrict__ partial) {
    __shared__ int s[SCAN_CHUNK];
    int i = blockIdx.x * SCAN_CHUNK + threadIdx.x;
    s[threadIdx.x] = (i < N_NODES) ? counts[i] : 0;
    __syncthreads();
    for (int st = SCAN_CHUNK / 2; st > 0; st >>= 1) {
        if (threadIdx.x < st) s[threadIdx.x] += s[threadIdx.x + st];
        __syncthreads();
    }
    if (threadIdx.x == 0) partial[blockIdx.x] = s[0];
}

// ---------------------------------------------------------------------------
// Scan stage 2 (fused): every block redundantly scans the partials in smem,
// then does its chunk's exclusive scan -> rowptr, cursor.
// ---------------------------------------------------------------------------
__global__ void scan_final(const int* __restrict__ counts,
                           const int* __restrict__ partial,
                           int* __restrict__ rowptr,
                           int* __restrict__ cursor, int nnz) {
    __shared__ int sp[256];
    __shared__ int s[SCAN_CHUNK];

    if (threadIdx.x < 256) {
        int v = (threadIdx.x < NCHUNK) ? partial[threadIdx.x] : 0;
        sp[threadIdx.x] = v;
    }
    __syncthreads();
    for (int st = 1; st < 256; st <<= 1) {
        int t = 0;
        if (threadIdx.x < 256 && threadIdx.x >= st) t = sp[threadIdx.x - st];
        __syncthreads();
        if (threadIdx.x < 256) sp[threadIdx.x] += t;
        __syncthreads();
    }
    int block_ex = (blockIdx.x == 0) ? 0 : sp[blockIdx.x - 1];

    int i = blockIdx.x * SCAN_CHUNK + threadIdx.x;
    int v = (i < N_NODES) ? counts[i] : 0;
    s[threadIdx.x] = v;
    __syncthreads();
    for (int st = 1; st < SCAN_CHUNK; st <<= 1) {
        int t = (threadIdx.x >= st) ? s[threadIdx.x - st] : 0;
        __syncthreads();
        s[threadIdx.x] += t;
        __syncthreads();
    }
    if (i < N_NODES) {
        int ex = block_ex + s[threadIdx.x] - v;
        rowptr[i] = ex;
        cursor[i] = ex;
    }
    if (i == 0) rowptr[N_NODES] = nnz;
}

// ---------------------------------------------------------------------------
// Counting-sort stage 3: scatter edges (1 edge/thread, max TLP for atomics)
// ---------------------------------------------------------------------------
__global__ void scatter_kernel(const int* __restrict__ row,
                               const int* __restrict__ col,
                               const float* __restrict__ vals,
                               int* __restrict__ cursor,
                               int2* __restrict__ edges, int nnz) {
    int i = blockIdx.x * blockDim.x + threadIdx.x;
    if (i < nnz) {
        int r = __ldcs(row + i);
        int p = atomicAdd(&cursor[r], 1);
        edges[p] = make_int2(__ldcs(col + i), __float_as_int(__ldcs(vals + i)));
    }
}

// ---------------------------------------------------------------------------
// CSR SpMM, warp per row, fp16 gather (128 B/edge), fp32 accumulation.
// R9-proven body (unroll 4). NEW: __launch_bounds__(256, 8) caps regs at 32
// -> 64 warps/SM (R12 profile showed 40 regs / 60.7% occ / issue 35% =
// latency-bound; this is the occupancy fix).
// FINAL=false: y[row] = h (fp16)
// FINAL=true : out[row] = (ego + h1 + h2 + h) * 0.25  (fp32), no y store
// ---------------------------------------------------------------------------
template<bool FINAL>
__global__ void __launch_bounds__(256, 8)
spmm_csr(const int* __restrict__ rowptr,
         const int2* __restrict__ edges,
         const __half* __restrict__ x,     // gather source
         __half* __restrict__ y,           // !FINAL
         const __half* __restrict__ ego,   // FINAL
         const __half* __restrict__ h1,    // FINAL
         float* __restrict__ out) {        // FINAL
    int warp = (blockIdx.x * blockDim.x + threadIdx.x) >> 5;
    int lane = threadIdx.x & 31;
    if (warp >= N_NODES) return;

    int start = __ldg(rowptr + warp);
    int end   = __ldg(rowptr + warp + 1);

    float ax = 0.f, ay = 0.f;
    int e = start;

    #define XR(c) (reinterpret_cast<const __half2*>(x + (size_t)(c) * EMB) + lane)

    for (; e + 4 <= end; e += 4) {
        int2 e0 = __ldg(edges + e + 0);
        int2 e1 = __ldg(edges + e + 1);
        int2 e2 = __ldg(edges + e + 2);
        int2 e3 = __ldg(edges + e + 3);
        float2 x0 = __half22float2(__ldg(XR(e0.x)));
        float2 x1 = __half22float2(__ldg(XR(e1.x)));
        float2 x2 = __half22float2(__ldg(XR(e2.x)));
        float2 x3 = __half22float2(__ldg(XR(e3.x)));
        ax = fmaf(__int_as_float(e0.y), x0.x, ax);
        ay = fmaf(__int_as_float(e0.y), x0.y, ay);
        ax = fmaf(__int_as_float(e1.y), x1.x, ax);
        ay = fmaf(__int_as_float(e1.y), x1.y, ay);
        ax = fmaf(__int_as_float(e2.y), x2.x, ax);
        ay = fmaf(__int_as_float(e2.y), x2.y, ay);
        ax = fmaf(__int_as_float(e3.y), x3.x, ax);
        ay = fmaf(__int_as_float(e3.y), x3.y, ay);
    }
    for (; e < end; ++e) {
        int2 ed = __ldg(edges + e);
        float2 xv = __half22float2(__ldg(XR(ed.x)));
        float v = __int_as_float(ed.y);
        ax = fmaf(v, xv.x, ax);
        ay = fmaf(v, xv.y, ay);
    }
    #undef XR

    if (!FINAL) {
        reinterpret_cast<__half2*>(y + (size_t)warp * EMB)[lane] =
            __floats2half2_rn(ax, ay);
    } else {
        float2 eg = __half22float2(
            __ldg(reinterpret_cast<const __half2*>(ego + (size_t)warp * EMB) + lane));
        float2 a1 = __half22float2(
            __ldg(reinterpret_cast<const __half2*>(h1 + (size_t)warp * EMB) + lane));
        float2 a2 = __half22float2(
            __ldg(reinterpret_cast<const __half2*>(x + (size_t)warp * EMB) + lane));
        float2 o;
        o.x = (eg.x + a1.x + a2.x + ax) * 0.25f;
        o.y = (eg.y + a1.y + a2.y + ay) * 0.25f;
        reinterpret_cast<float2*>(out + (size_t)warp * EMB)[lane] = o;
    }
}

extern "C" void kernel_launch(void* const* d_in, const int* in_sizes, int n_in,
                              void* d_out, int out_size) {
    const float* user_emb = (const float*)d_in[0];
    const float* item_emb = (const float*)d_in[1];
    const int*   adj_row  = (const int*)  d_in[2];
    const int*   adj_col  = (const int*)  d_in[3];
    const float* adj_vals = (const float*)d_in[4];
    float* out = (float*)d_out;
    int nnz = in_sizes[2];

    __half* ego;   cudaGetSymbolAddress((void**)&ego,    g_ego);
    __half* h1;    cudaGetSymbolAddress((void**)&h1,     g_h1);
    __half* h2;    cudaGetSymbolAddress((void**)&h2,     g_h2);
    int*   rowptr; cudaGetSymbolAddress((void**)&rowptr, g_rowptr);
    int*   cursor; cudaGetSymbolAddress((void**)&cursor, g_cursor);
    int*   counts; cudaGetSymbolAddress((void**)&counts, g_counts);
    int2*  edges;  cudaGetSymbolAddress((void**)&edges,  g_edges);
    int*   partial;cudaGetSymbolAddress((void**)&partial,g_partial);

    const int T = 256;
    const int ZC_BLOCKS = (N_NODES + T - 1) / T;
    const int CH_BLOCKS = ((TOT / 2 > nnz ? TOT / 2 : nnz) + T - 1) / T;
    const int EG_BLOCKS = (nnz + T - 1) / T;
    const int SP_BLOCKS = (N_NODES * 32 + T - 1) / T;    // warp per row

    zero_counts<<<ZC_BLOCKS, T>>>(counts);
    conv_hist<<<CH_BLOCKS, T>>>((const float2*)user_emb, (const float2*)item_emb,
                                (__half2*)ego, adj_row, counts, nnz);
    scan_reduce<<<NCHUNK, SCAN_CHUNK>>>(counts, partial);
    scan_final<<<NCHUNK, SCAN_CHUNK>>>(counts, partial, rowptr, cursor, nnz);
    scatter_kernel<<<EG_BLOCKS, T>>>(adj_row, adj_col, adj_vals, cursor, edges, nnz);

    // layer 1: h1 = A*ego
    spmm_csr<false><<<SP_BLOCKS, T>>>(rowptr, edges, ego, h1, nullptr, nullptr, nullptr);
    // layer 2: h2 = A*h1
    spmm_csr<false><<<SP_BLOCKS, T>>>(rowptr, edges, h1, h2, nullptr, nullptr, nullptr);
    // layer 3: out = (ego + h1 + h2 + A*h2) / 4
    spmm_csr<true><<<SP_BLOCKS, T>>>(rowptr, edges, h2, nullptr, ego, h1, out);
}

// round 14
// speedup vs baseline: 1.5212x; 1.1123x over previous
#include <cuda_runtime.h>
#include <cuda_fp16.h>
#include <cuda_bf16.h>
#include <cstdint>

#define USER_NUM 100000
#define ITEM_NUM 50000
#define N_NODES  (USER_NUM + ITEM_NUM)   // 150000
#define EMB      64
#define TOT      (N_NODES * EMB)         // 9,600,000 elements
#define USER_ELEMS (USER_NUM * EMB)
#define NNZ_MAX  4800000
#define SCAN_CHUNK 1024
#define NCHUNK   ((N_NODES + SCAN_CHUNK - 1) / SCAN_CHUNK)   // 147

// Static device scratch (no runtime allocation allowed)
__device__ __half g_ego[TOT];            // fp16 copy of concat(user,item)
__device__ __half g_h1[TOT];             // layer-1 output (fp16)
__device__ __half g_h2[TOT];             // layer-2 output (fp16)
__device__ int   g_rowptr[N_NODES + 1];
__device__ int   g_cursor[N_NODES];
__device__ int   g_counts[N_NODES];
__device__ __align__(16) int2 g_edges[NNZ_MAX];  // (col, val-bits), row-sorted
__device__ int   g_partial[256];

// ---------------------------------------------------------------------------
// zero the row histogram
// ---------------------------------------------------------------------------
__global__ void zero_counts(int* __restrict__ counts) {
    int i = blockIdx.x * blockDim.x + threadIdx.x;
    if (i < N_NODES) counts[i] = 0;
}

// ---------------------------------------------------------------------------
// FUSED: convert ego -> fp16  +  per-row histogram. 1 edge/thread (max TLP
// for the atomics — R11 lesson: never batch atomics per thread).
// ---------------------------------------------------------------------------
__global__ void conv_hist(const float2* __restrict__ user2,
                          const float2* __restrict__ item2,
                          __half2* __restrict__ ego2,
                          const int* __restrict__ row,
                          int* __restrict__ counts, int nnz) {
    int i = blockIdx.x * blockDim.x + threadIdx.x;
    if (i < TOT / 2) {
        float2 v = (i < USER_ELEMS / 2) ? __ldg(user2 + i)
                                        : __ldg(item2 + (i - USER_ELEMS / 2));
        ego2[i] = __floats2half2_rn(v.x, v.y);
    }
    if (i < nnz) atomicAdd(&counts[__ldcs(row + i)], 1);
}

// ---------------------------------------------------------------------------
// Scan stage 1: per-chunk sums (147 partials)
// ---------------------------------------------------------------------------
__global__ void scan_reduce(const int* __restrict__ counts,
                            int* __restrict__ partial) {
    __shared__ int s[SCAN_CHUNK];
    int i = blockIdx.x * SCAN_CHUNK + threadIdx.x;
    s[threadIdx.x] = (i < N_NODES) ? counts[i] : 0;
    __syncthreads();
    for (int st = SCAN_CHUNK / 2; st > 0; st >>= 1) {
        if (threadIdx.x < st) s[threadIdx.x] += s[threadIdx.x + st];
        __syncthreads();
    }
    if (threadIdx.x == 0) partial[blockIdx.x] = s[0];
}

// ---------------------------------------------------------------------------
// Scan stage 2 (fused): every block redundantly scans the partials in smem,
// then does its chunk's exclusive scan -> rowptr, cursor.
// ---------------------------------------------------------------------------
__global__ void scan_final(const int* __restrict__ counts,
                           const int* __restrict__ partial,
                           int* __restrict__ rowptr,
                           int* __restrict__ cursor, int nnz) {
    __shared__ int sp[256];
    __shared__ int s[SCAN_CHUNK];

    if (threadIdx.x < 256) {
        int v = (threadIdx.x < NCHUNK) ? partial[threadIdx.x] : 0;
        sp[threadIdx.x] = v;
    }
    __syncthreads();
    for (int st = 1; st < 256; st <<= 1) {
        int t = 0;
        if (threadIdx.x < 256 && threadIdx.x >= st) t = sp[threadIdx.x - st];
        __syncthreads();
        if (threadIdx.x < 256) sp[threadIdx.x] += t;
        __syncthreads();
    }
    int block_ex = (blockIdx.x == 0) ? 0 : sp[blockIdx.x - 1];

    int i = blockIdx.x * SCAN_CHUNK + threadIdx.x;
    int v = (i < N_NODES) ? counts[i] : 0;
    s[threadIdx.x] = v;
    __syncthreads();
    for (int st = 1; st < SCAN_CHUNK; st <<= 1) {
        int t = (threadIdx.x >= st) ? s[threadIdx.x - st] : 0;
        __syncthreads();
        s[threadIdx.x] += t;
        __syncthreads();
    }
    if (i < N_NODES) {
        int ex = block_ex + s[threadIdx.x] - v;
        rowptr[i] = ex;
        cursor[i] = ex;
    }
    if (i == 0) rowptr[N_NODES] = nnz;
}

// ---------------------------------------------------------------------------
// Counting-sort stage 3: scatter edges (1 edge/thread, max TLP for atomics)
// ---------------------------------------------------------------------------
__global__ void scatter_kernel(const int* __restrict__ row,
                               const int* __restrict__ col,
                               const float* __restrict__ vals,
                               int* __restrict__ cursor,
                               int2* __restrict__ edges, int nnz) {
    int i = blockIdx.x * blockDim.x + threadIdx.x;
    if (i < nnz) {
        int r = __ldcs(row + i);
        int p = atomicAdd(&cursor[r], 1);
        edges[p] = make_int2(__ldcs(col + i), __float_as_int(__ldcs(vals + i)));
    }
}

// ---------------------------------------------------------------------------
// CSR SpMM, warp per row, fp16 gather (128 B/edge), fp32 accumulation.
// R14 change: edge metadata loaded as warp-uniform int4 (2 edges per LDG)
// — halves edge-meta wavefronts; the GATHER pattern is byte-identical to the
// R9-proven config (lane owns a __half2, 4 gathers in flight).
// FINAL=false: y[row] = h (fp16)
// FINAL=true : out[row] = (ego + h1 + h2 + h) * 0.25  (fp32), no y store
// ---------------------------------------------------------------------------
template<bool FINAL>
__global__ void __launch_bounds__(256, 8)
spmm_csr(const int* __restrict__ rowptr,
         const int2* __restrict__ edges,
         const __half* __restrict__ x,     // gather source
         __half* __restrict__ y,           // !FINAL
         const __half* __restrict__ ego,   // FINAL
         const __half* __restrict__ h1,    // FINAL
         float* __restrict__ out) {        // FINAL
    int warp = (blockIdx.x * blockDim.x + threadIdx.x) >> 5;
    int lane = threadIdx.x & 31;
    if (warp >= N_NODES) return;

    int start = __ldg(rowptr + warp);
    int end   = __ldg(rowptr + warp + 1);

    float ax = 0.f, ay = 0.f;

    #define XR(c) (reinterpret_cast<const __half2*>(x + (size_t)(c) * EMB) + lane)
    #define ACC_EDGE(col_, vbits_) do {                                   \
        float2 xv_ = __half22float2(__ldg(XR(col_)));                     \
        float v_ = __int_as_float(vbits_);                                \
        ax = fmaf(v_, xv_.x, ax);                                         \
        ay = fmaf(v_, xv_.y, ay);                                         \
    } while (0)

    int e = start;
    // align to even index for 16B int4 loads
    if ((e & 1) && e < end) {
        int2 ed = __ldg(edges + e);
        ACC_EDGE(ed.x, ed.y);
        e++;
    }

    // 4 edges per iter via 2 warp-uniform int4 loads; 4 gathers in flight
    for (; e + 4 <= end; e += 4) {
        int4 q0 = __ldg(reinterpret_cast<const int4*>(edges + e));
        int4 q1 = __ldg(reinterpret_cast<const int4*>(edges + e + 2));
        float2 x0 = __half22float2(__ldg(XR(q0.x)));
        float2 x1 = __half22float2(__ldg(XR(q0.z)));
        float2 x2 = __half22float2(__ldg(XR(q1.x)));
        float2 x3 = __half22float2(__ldg(XR(q1.z)));
        ax = fmaf(__int_as_float(q0.y), x0.x, ax);
        ay = fmaf(__int_as_float(q0.y), x0.y, ay);
        ax = fmaf(__int_as_float(q0.w), x1.x, ax);
        ay = fmaf(__int_as_float(q0.w), x1.y, ay);
        ax = fmaf(__int_as_float(q1.y), x2.x, ax);
        ay = fmaf(__int_as_float(q1.y), x2.y, ay);
        ax = fmaf(__int_as_float(q1.w), x3.x, ax);
        ay = fmaf(__int_as_float(q1.w), x3.y, ay);
    }
    // remaining aligned pair
    if (e + 2 <= end) {
        int4 q0 = __ldg(reinterpret_cast<const int4*>(edges + e));
        float2 x0 = __half22float2(__ldg(XR(q0.x)));
        float2 x1 = __half22float2(__ldg(XR(q0.z)));
        ax = fmaf(__int_as_float(q0.y), x0.x, ax);
        ay = fmaf(__int_as_float(q0.y), x0.y, ay);
        ax = fmaf(__int_as_float(q0.w), x1.x, ax);
        ay = fmaf(__int_as_float(q0.w), x1.y, ay);
        e += 2;
    }
    // trailing edge
    if (e < end) {
        int2 ed = __ldg(edges + e);
        ACC_EDGE(ed.x, ed.y);
    }
    #undef ACC_EDGE
    #undef XR

    if (!FINAL) {
        reinterpret_cast<__half2*>(y + (size_t)warp * EMB)[lane] =
            __floats2half2_rn(ax, ay);
    } else {
        float2 eg = __half22float2(
            __ldg(reinterpret_cast<const __half2*>(ego + (size_t)warp * EMB) + lane));
        float2 a1 = __half22float2(
            __ldg(reinterpret_cast<const __half2*>(h1 + (size_t)warp * EMB) + lane));
        float2 a2 = __half22float2(
            __ldg(reinterpret_cast<const __half2*>(x + (size_t)warp * EMB) + lane));
        float2 o;
        o.x = (eg.x + a1.x + a2.x + ax) * 0.25f;
        o.y = (eg.y + a1.y + a2.y + ay) * 0.25f;
        reinterpret_cast<float2*>(out + (size_t)warp * EMB)[lane] = o;
    }
}

extern "C" void kernel_launch(void* const* d_in, const int* in_sizes, int n_in,
                              void* d_out, int out_size) {
    const float* user_emb = (const float*)d_in[0];
    const float* item_emb = (const float*)d_in[1];
    const int*   adj_row  = (const int*)  d_in[2];
    const int*   adj_col  = (const int*)  d_in[3];
    const float* adj_vals = (const float*)d_in[4];
    float* out = (float*)d_out;
    int nnz = in_sizes[2];

    __half* ego;   cudaGetSymbolAddress((void**)&ego,    g_ego);
    __half* h1;    cudaGetSymbolAddress((void**)&h1,     g_h1);
    __half* h2;    cudaGetSymbolAddress((void**)&h2,     g_h2);
    int*   rowptr; cudaGetSymbolAddress((void**)&rowptr, g_rowptr);
    int*   cursor; cudaGetSymbolAddress((void**)&cursor, g_cursor);
    int*   counts; cudaGetSymbolAddress((void**)&counts, g_counts);
    int2*  edges;  cudaGetSymbolAddress((void**)&edges,  g_edges);
    int*   partial;cudaGetSymbolAddress((void**)&partial,g_partial);

    const int T = 256;
    const int ZC_BLOCKS = (N_NODES + T - 1) / T;
    const int CH_BLOCKS = ((TOT / 2 > nnz ? TOT / 2 : nnz) + T - 1) / T;
    const int EG_BLOCKS = (nnz + T - 1) / T;
    const int SP_BLOCKS = (N_NODES * 32 + T - 1) / T;    // warp per row

    zero_counts<<<ZC_BLOCKS, T>>>(counts);
    conv_hist<<<CH_BLOCKS, T>>>((const float2*)user_emb, (const float2*)item_emb,
                                (__half2*)ego, adj_row, counts, nnz);
    scan_reduce<<<NCHUNK, SCAN_CHUNK>>>(counts, partial);
    scan_final<<<NCHUNK, SCAN_CHUNK>>>(counts, partial, rowptr, cursor, nnz);
    scatter_kernel<<<EG_BLOCKS, T>>>(adj_row, adj_col, adj_vals, cursor, edges, nnz);

    // layer 1: h1 = A*ego
    spmm_csr<false><<<SP_BLOCKS, T>>>(rowptr, edges, ego, h1, nullptr, nullptr, nullptr);
    // layer 2: h2 = A*h1
    spmm_csr<false><<<SP_BLOCKS, T>>>(rowptr, edges, h1, h2, nullptr, nullptr, nullptr);
    // layer 3: out = (ego + h1 + h2 + A*h2) / 4
    spmm_csr<true><<<SP_BLOCKS, T>>>(rowptr, edges, h2, nullptr, ego, h1, out);
}